// round 8
// baseline (speedup 1.0000x reference)
#include <cuda_runtime.h>

#define N_NODES 100000
#define D_IN 512
#define DH 20
#define DH2 40
#define D_OUT 128
#define EMAX 3200000

// ---------------- scratch (device globals: no allocs allowed) ----------------
__device__ __align__(16) float g_xts[(size_t)N_NODES * DH2];  // (x@[W1|W2]) * dinv[row]
__device__ __align__(16) float g_agg[(size_t)N_NODES * DH2];  // aggregated + self + bias
__device__ float g_dinv[N_NODES];
__device__ int   g_deg [N_NODES];
__device__ int   g_cur [N_NODES];        // cursor, initialized to offsets by scan
__device__ int   g_off [N_NODES + 1];    // stable CSR offsets
__device__ int   g_sr  [EMAX];           // src per edge, CSR-ordered by dst

// ---------------- degree histogram ----------------
__global__ void k_zero() {
    int i = blockIdx.x * blockDim.x + threadIdx.x;
    if (i < N_NODES) g_deg[i] = 0;
}
__global__ void k_count(const int* __restrict__ dst, int E) {
    int e = blockIdx.x * blockDim.x + threadIdx.x;
    if (e < E) atomicAdd(&g_deg[dst[e]], 1);
}

// ---------------- exclusive scan (1 block) + dinv + cursor init -------------
#define SCT 1024
#define SCCH ((N_NODES + SCT - 1) / SCT)   // 98
__global__ __launch_bounds__(SCT) void k_scan() {
    __shared__ int sh[SCT];
    const int t = threadIdx.x;
    const int base = t * SCCH;
    int s = 0;
    for (int i = 0; i < SCCH; i++) {
        int idx = base + i;
        if (idx < N_NODES) s += g_deg[idx];
    }
    sh[t] = s;
    __syncthreads();
    for (int o = 1; o < SCT; o <<= 1) {
        int v = (t >= o) ? sh[t - o] : 0;
        __syncthreads();
        sh[t] += v;
        __syncthreads();
    }
    int run = sh[t] - s;   // exclusive prefix of this chunk
    for (int i = 0; i < SCCH; i++) {
        int idx = base + i;
        if (idx < N_NODES) {
            int d = g_deg[idx];
            g_off[idx]  = run;
            g_cur[idx]  = run;                       // cursor starts at offset
            g_dinv[idx] = rsqrtf((float)d + 1.0f);
            run += d;
        }
    }
    if (t == SCT - 1) g_off[N_NODES] = sh[SCT - 1];
}

// ---------------- CSR fill: src-only records, single atomic per edge --------
__global__ void k_fill(const int* __restrict__ src,
                       const int* __restrict__ dst, int E) {
    int e = blockIdx.x * blockDim.x + threadIdx.x;
    if (e >= E) return;
    int s = src[e];
    int d = dst[e];
    int pos = atomicAdd(&g_cur[d], 1);   // cursor pre-seeded with offset
    g_sr[pos] = s;
}

// ---------------- xts = (x @ [W1|W2]) * dinv  (fp32 FMA, float4 weights) ----
#define GT  64
#define GR  128
#define GKB 16

__global__ __launch_bounds__(GT) void k_gemm(
        const float* __restrict__ x,
        const float* __restrict__ W1,
        const float* __restrict__ W2) {
    __shared__ __align__(16) float  xs[GKB][GR + 4];   // transposed x tile
    __shared__ __align__(16) float4 ws4[GKB][DH2 / 4]; // weight chunk, vectorized

    const int tid  = threadIdx.x;
    const int row0 = blockIdx.x * GR;

    float acc0[DH2], acc1[DH2];
    #pragma unroll
    for (int c = 0; c < DH2; c++) { acc0[c] = 0.f; acc1[c] = 0.f; }

    for (int kb = 0; kb < D_IN; kb += GKB) {
        __syncthreads();
        // weight chunk: GKB*40 floats into float4-layout smem
        for (int i = tid; i < GKB * DH2; i += GT) {
            int kk = i / DH2, c = i % DH2;
            ((float*)ws4)[(size_t)kk * DH2 + c] =
                (c < DH) ? W1[(size_t)(kb + kk) * DH + c]
                         : W2[(size_t)(kb + kk) * DH + (c - DH)];
        }
        // x tile: 128 rows x 16 k, transposed into smem
        #pragma unroll
        for (int j = 0; j < GR / GT; j++) {
            int r  = tid + GT * j;
            int gr = row0 + r;
            if (gr < N_NODES) {
                const float4* srcp = (const float4*)(x + (size_t)gr * D_IN + kb);
                #pragma unroll
                for (int q = 0; q < GKB / 4; q++) {
                    float4 v = srcp[q];
                    xs[q*4+0][r] = v.x; xs[q*4+1][r] = v.y;
                    xs[q*4+2][r] = v.z; xs[q*4+3][r] = v.w;
                }
            } else {
                #pragma unroll
                for (int q = 0; q < GKB; q++) xs[q][r] = 0.f;
            }
        }
        __syncthreads();

        #pragma unroll 4
        for (int kk = 0; kk < GKB; kk++) {
            float2 xv = *(const float2*)&xs[kk][tid * 2];  // 2 rows, LDS.64
            #pragma unroll
            for (int j = 0; j < DH2 / 4; j++) {
                float4 w = ws4[kk][j];                      // LDS.128 broadcast
                acc0[j*4+0] = fmaf(xv.x, w.x, acc0[j*4+0]);
                acc0[j*4+1] = fmaf(xv.x, w.y, acc0[j*4+1]);
                acc0[j*4+2] = fmaf(xv.x, w.z, acc0[j*4+2]);
                acc0[j*4+3] = fmaf(xv.x, w.w, acc0[j*4+3]);
                acc1[j*4+0] = fmaf(xv.y, w.x, acc1[j*4+0]);
                acc1[j*4+1] = fmaf(xv.y, w.y, acc1[j*4+1]);
                acc1[j*4+2] = fmaf(xv.y, w.z, acc1[j*4+2]);
                acc1[j*4+3] = fmaf(xv.y, w.w, acc1[j*4+3]);
            }
        }
    }

    // epilogue: write xts = acc * dinv[row]
    #pragma unroll
    for (int h = 0; h < 2; h++) {
        int row = row0 + tid * 2 + h;
        if (row < N_NODES) {
            float di = g_dinv[row];
            float* xo = g_xts + (size_t)row * DH2;
            const float* ac = h ? acc1 : acc0;
            #pragma unroll
            for (int c4 = 0; c4 < DH2 / 4; c4++) {
                float4 vv;
                vv.x = ac[c4*4+0] * di; vv.y = ac[c4*4+1] * di;
                vv.z = ac[c4*4+2] * di; vv.w = ac[c4*4+3] * di;
                *(float4*)(xo + c4*4) = vv;
            }
        }
    }
}

// ---------------- gather: agg[n] = dinv[n]*(sum_e xts[src_e] + xts[n]) + b --
// 320 threads = 32 nodes x 10 quads; each (node,quad) owned by one thread.
#define GA_NODES 32
__global__ __launch_bounds__(320) void k_gather(const float* __restrict__ b1,
                                                const float* __restrict__ b2) {
    __shared__ float bsm[DH2];
    const int tid = threadIdx.x;
    if (tid < DH2) bsm[tid] = (tid < DH) ? b1[tid] : b2[tid - DH];
    __syncthreads();

    const int nl = tid / 10, q = tid % 10;
    const int n = blockIdx.x * GA_NODES + nl;
    if (n >= N_NODES) return;

    const int e0 = g_off[n], e1 = g_off[n + 1];
    const float4* selfq = (const float4*)(g_xts + (size_t)n * DH2 + q * 4);
    float4 acc = *selfq;    // self-loop term (xts[n]; scaled by dinv[n] below)

    int e = e0;
    for (; e + 1 < e1; e += 2) {
        int s0 = g_sr[e], s1 = g_sr[e + 1];
        float4 v0 = *(const float4*)(g_xts + (size_t)s0 * DH2 + q * 4);
        float4 v1 = *(const float4*)(g_xts + (size_t)s1 * DH2 + q * 4);
        acc.x += v0.x + v1.x; acc.y += v0.y + v1.y;
        acc.z += v0.z + v1.z; acc.w += v0.w + v1.w;
    }
    if (e < e1) {
        float4 v = *(const float4*)(g_xts + (size_t)g_sr[e] * DH2 + q * 4);
        acc.x += v.x; acc.y += v.y; acc.z += v.z; acc.w += v.w;
    }

    float di = g_dinv[n];
    float4 bq = *(const float4*)&bsm[q * 4];
    float4 r;
    r.x = fmaf(acc.x, di, bq.x); r.y = fmaf(acc.y, di, bq.y);
    r.z = fmaf(acc.z, di, bq.z); r.w = fmaf(acc.w, di, bq.w);
    *(float4*)(g_agg + (size_t)n * DH2 + q * 4) = r;
}

// ---------------- m = agg @ Wl + bl ; l2norm ----------------
__global__ __launch_bounds__(128) void k_final(
        const float* __restrict__ Wl1, const float* __restrict__ bl1,
        const float* __restrict__ Wl2, const float* __restrict__ bl2,
        float* __restrict__ out) {
    __shared__ __align__(16) float ws[2 * DH * D_OUT];
    __shared__ __align__(16) float bs[2][D_OUT];
    const int tid = threadIdx.x;

    for (int i = tid; i < DH * D_OUT; i += 128) {
        ws[i]              = Wl1[i];
        ws[DH * D_OUT + i] = Wl2[i];
    }
    bs[0][tid] = bl1[tid];
    bs[1][tid] = bl2[tid];
    __syncthreads();

    int node = blockIdx.x * 128 + tid;
    if (node >= N_NODES) return;
    const float* arow = g_agg + (size_t)node * DH2;

    #pragma unroll 1
    for (int ch = 0; ch < 2; ch++) {
        float4 m[D_OUT / 4];
        #pragma unroll
        for (int j = 0; j < D_OUT / 4; j++) m[j] = *(const float4*)&bs[ch][j*4];

        const float* a   = arow + ch * DH;
        const float* wch = ws + ch * DH * D_OUT;
        #pragma unroll 4
        for (int k = 0; k < DH; k++) {
            float ak = a[k];
            const float* wrow = wch + k * D_OUT;
            #pragma unroll
            for (int j = 0; j < D_OUT / 4; j++) {
                float4 w = *(const float4*)&wrow[j*4];
                m[j].x = fmaf(ak, w.x, m[j].x);
                m[j].y = fmaf(ak, w.y, m[j].y);
                m[j].z = fmaf(ak, w.z, m[j].z);
                m[j].w = fmaf(ak, w.w, m[j].w);
            }
        }
        float ssq = 0.f;
        #pragma unroll
        for (int j = 0; j < D_OUT / 4; j++)
            ssq += m[j].x*m[j].x + m[j].y*m[j].y + m[j].z*m[j].z + m[j].w*m[j].w;
        float inv = 1.0f / fmaxf(sqrtf(ssq), 1e-12f);

        float4* o = (float4*)(out + (size_t)ch * N_NODES * D_OUT + (size_t)node * D_OUT);
        #pragma unroll
        for (int j = 0; j < D_OUT / 4; j++) {
            float4 r = m[j];
            r.x *= inv; r.y *= inv; r.z *= inv; r.w *= inv;
            o[j] = r;
        }
    }
}

// ---------------- launch ----------------
extern "C" void kernel_launch(void* const* d_in, const int* in_sizes, int n_in,
                              void* d_out, int out_size) {
    const float* x   = (const float*)d_in[0];
    const int*   ei  = (const int*)d_in[1];     // int32 (JAX x64 disabled)
    const float* W1  = (const float*)d_in[2];
    const float* b1  = (const float*)d_in[3];
    const float* W2  = (const float*)d_in[4];
    const float* b2  = (const float*)d_in[5];
    const float* Wl1 = (const float*)d_in[6];
    const float* bl1 = (const float*)d_in[7];
    const float* Wl2 = (const float*)d_in[8];
    const float* bl2 = (const float*)d_in[9];
    float* out = (float*)d_out;

    int E = in_sizes[1] / 2;
    if (E > EMAX) E = EMAX;
    const int* srcp = ei;
    const int* dstp = ei + E;

    k_zero  <<<(N_NODES + 255) / 256, 256>>>();
    k_count <<<(E + 255) / 256, 256>>>(dstp, E);
    k_scan  <<<1, SCT>>>();
    k_fill  <<<(E + 255) / 256, 256>>>(srcp, dstp, E);
    k_gemm  <<<(N_NODES + GR - 1) / GR, GT>>>(x, W1, W2);
    k_gather<<<(N_NODES + GA_NODES - 1) / GA_NODES, 320>>>(b1, b2);
    k_final <<<(N_NODES + 127) / 128, 128>>>(Wl1, bl1, Wl2, bl2, out);
}

// round 9
// speedup vs baseline: 1.0007x; 1.0007x over previous
#include <cuda_runtime.h>

#define N_NODES 100000
#define D_IN 512
#define DH 20
#define DH2 40
#define D_OUT 128
#define EMAX 3200000

// ---------------- scratch (device globals: no allocs allowed) ----------------
__device__ __align__(16) float g_xts[(size_t)N_NODES * DH2];  // (x@[W1|W2]) * dinv[row]
__device__ __align__(16) float g_agg[(size_t)N_NODES * DH2];  // aggregated + self + bias
__device__ float g_dinv[N_NODES];
__device__ int   g_deg [N_NODES];
__device__ int   g_cur [N_NODES];        // cursor, initialized to offsets by scan
__device__ int   g_off [N_NODES + 1];    // stable CSR offsets
__device__ int   g_sr  [EMAX];           // src per edge, CSR-ordered by dst

// ---------------- degree histogram ----------------
__global__ void k_zero() {
    int i = blockIdx.x * blockDim.x + threadIdx.x;
    if (i < N_NODES) g_deg[i] = 0;
}
__global__ void k_count(const int* __restrict__ dst, int E) {
    int e = blockIdx.x * blockDim.x + threadIdx.x;
    if (e < E) atomicAdd(&g_deg[dst[e]], 1);
}

// ---------------- exclusive scan (1 block) + dinv + cursor init -------------
#define SCT 1024
#define SCCH ((N_NODES + SCT - 1) / SCT)   // 98
__global__ __launch_bounds__(SCT) void k_scan() {
    __shared__ int sh[SCT];
    const int t = threadIdx.x;
    const int base = t * SCCH;
    int s = 0;
    for (int i = 0; i < SCCH; i++) {
        int idx = base + i;
        if (idx < N_NODES) s += g_deg[idx];
    }
    sh[t] = s;
    __syncthreads();
    for (int o = 1; o < SCT; o <<= 1) {
        int v = (t >= o) ? sh[t - o] : 0;
        __syncthreads();
        sh[t] += v;
        __syncthreads();
    }
    int run = sh[t] - s;   // exclusive prefix of this chunk
    for (int i = 0; i < SCCH; i++) {
        int idx = base + i;
        if (idx < N_NODES) {
            int d = g_deg[idx];
            g_off[idx]  = run;
            g_cur[idx]  = run;                       // cursor starts at offset
            g_dinv[idx] = rsqrtf((float)d + 1.0f);
            run += d;
        }
    }
    if (t == SCT - 1) g_off[N_NODES] = sh[SCT - 1];
}

// ---------------- CSR fill: src-only records, single atomic per edge --------
__global__ void k_fill(const int* __restrict__ src,
                       const int* __restrict__ dst, int E) {
    int e = blockIdx.x * blockDim.x + threadIdx.x;
    if (e >= E) return;
    int s = src[e];
    int d = dst[e];
    int pos = atomicAdd(&g_cur[d], 1);   // cursor pre-seeded with offset
    g_sr[pos] = s;
}

// ---------------- xts = (x @ [W1|W2]) * dinv  (fp32 FMA, float4 weights) ----
#define GT  64
#define GR  128
#define GKB 16

__global__ __launch_bounds__(GT) void k_gemm(
        const float* __restrict__ x,
        const float* __restrict__ W1,
        const float* __restrict__ W2) {
    __shared__ __align__(16) float  xs[GKB][GR + 4];   // transposed x tile
    __shared__ __align__(16) float4 ws4[GKB][DH2 / 4]; // weight chunk, vectorized

    const int tid  = threadIdx.x;
    const int row0 = blockIdx.x * GR;

    float acc0[DH2], acc1[DH2];
    #pragma unroll
    for (int c = 0; c < DH2; c++) { acc0[c] = 0.f; acc1[c] = 0.f; }

    for (int kb = 0; kb < D_IN; kb += GKB) {
        __syncthreads();
        // weight chunk: GKB*40 floats into float4-layout smem
        for (int i = tid; i < GKB * DH2; i += GT) {
            int kk = i / DH2, c = i % DH2;
            ((float*)ws4)[(size_t)kk * DH2 + c] =
                (c < DH) ? W1[(size_t)(kb + kk) * DH + c]
                         : W2[(size_t)(kb + kk) * DH + (c - DH)];
        }
        // x tile: 128 rows x 16 k, transposed into smem
        #pragma unroll
        for (int j = 0; j < GR / GT; j++) {
            int r  = tid + GT * j;
            int gr = row0 + r;
            if (gr < N_NODES) {
                const float4* srcp = (const float4*)(x + (size_t)gr * D_IN + kb);
                #pragma unroll
                for (int q = 0; q < GKB / 4; q++) {
                    float4 v = srcp[q];
                    xs[q*4+0][r] = v.x; xs[q*4+1][r] = v.y;
                    xs[q*4+2][r] = v.z; xs[q*4+3][r] = v.w;
                }
            } else {
                #pragma unroll
                for (int q = 0; q < GKB; q++) xs[q][r] = 0.f;
            }
        }
        __syncthreads();

        #pragma unroll 4
        for (int kk = 0; kk < GKB; kk++) {
            float2 xv = *(const float2*)&xs[kk][tid * 2];  // 2 rows, LDS.64
            #pragma unroll
            for (int j = 0; j < DH2 / 4; j++) {
                float4 w = ws4[kk][j];                      // LDS.128 broadcast
                acc0[j*4+0] = fmaf(xv.x, w.x, acc0[j*4+0]);
                acc0[j*4+1] = fmaf(xv.x, w.y, acc0[j*4+1]);
                acc0[j*4+2] = fmaf(xv.x, w.z, acc0[j*4+2]);
                acc0[j*4+3] = fmaf(xv.x, w.w, acc0[j*4+3]);
                acc1[j*4+0] = fmaf(xv.y, w.x, acc1[j*4+0]);
                acc1[j*4+1] = fmaf(xv.y, w.y, acc1[j*4+1]);
                acc1[j*4+2] = fmaf(xv.y, w.z, acc1[j*4+2]);
                acc1[j*4+3] = fmaf(xv.y, w.w, acc1[j*4+3]);
            }
        }
    }

    // epilogue: write xts = acc * dinv[row]
    #pragma unroll
    for (int h = 0; h < 2; h++) {
        int row = row0 + tid * 2 + h;
        if (row < N_NODES) {
            float di = g_dinv[row];
            float* xo = g_xts + (size_t)row * DH2;
            const float* ac = h ? acc1 : acc0;
            #pragma unroll
            for (int c4 = 0; c4 < DH2 / 4; c4++) {
                float4 vv;
                vv.x = ac[c4*4+0] * di; vv.y = ac[c4*4+1] * di;
                vv.z = ac[c4*4+2] * di; vv.w = ac[c4*4+3] * di;
                *(float4*)(xo + c4*4) = vv;
            }
        }
    }
}

// ---------------- gather: agg[n] = dinv[n]*(sum_e xts[src_e] + xts[n]) + b --
// 320 threads = 32 nodes x 10 quads; each (node,quad) owned by one thread.
#define GA_NODES 32
__global__ __launch_bounds__(320) void k_gather(const float* __restrict__ b1,
                                                const float* __restrict__ b2) {
    __shared__ float bsm[DH2];
    const int tid = threadIdx.x;
    if (tid < DH2) bsm[tid] = (tid < DH) ? b1[tid] : b2[tid - DH];
    __syncthreads();

    const int nl = tid / 10, q = tid % 10;
    const int n = blockIdx.x * GA_NODES + nl;
    if (n >= N_NODES) return;

    const int e0 = g_off[n], e1 = g_off[n + 1];
    const float4* selfq = (const float4*)(g_xts + (size_t)n * DH2 + q * 4);
    float4 acc = *selfq;    // self-loop term (xts[n]; scaled by dinv[n] below)

    int e = e0;
    for (; e + 1 < e1; e += 2) {
        int s0 = g_sr[e], s1 = g_sr[e + 1];
        float4 v0 = *(const float4*)(g_xts + (size_t)s0 * DH2 + q * 4);
        float4 v1 = *(const float4*)(g_xts + (size_t)s1 * DH2 + q * 4);
        acc.x += v0.x + v1.x; acc.y += v0.y + v1.y;
        acc.z += v0.z + v1.z; acc.w += v0.w + v1.w;
    }
    if (e < e1) {
        float4 v = *(const float4*)(g_xts + (size_t)g_sr[e] * DH2 + q * 4);
        acc.x += v.x; acc.y += v.y; acc.z += v.z; acc.w += v.w;
    }

    float di = g_dinv[n];
    float4 bq = *(const float4*)&bsm[q * 4];
    float4 r;
    r.x = fmaf(acc.x, di, bq.x); r.y = fmaf(acc.y, di, bq.y);
    r.z = fmaf(acc.z, di, bq.z); r.w = fmaf(acc.w, di, bq.w);
    *(float4*)(g_agg + (size_t)n * DH2 + q * 4) = r;
}

// ---------------- m = agg @ Wl + bl ; l2norm ----------------
__global__ __launch_bounds__(128) void k_final(
        const float* __restrict__ Wl1, const float* __restrict__ bl1,
        const float* __restrict__ Wl2, const float* __restrict__ bl2,
        float* __restrict__ out) {
    __shared__ __align__(16) float ws[2 * DH * D_OUT];
    __shared__ __align__(16) float bs[2][D_OUT];
    const int tid = threadIdx.x;

    for (int i = tid; i < DH * D_OUT; i += 128) {
        ws[i]              = Wl1[i];
        ws[DH * D_OUT + i] = Wl2[i];
    }
    bs[0][tid] = bl1[tid];
    bs[1][tid] = bl2[tid];
    __syncthreads();

    int node = blockIdx.x * 128 + tid;
    if (node >= N_NODES) return;
    const float* arow = g_agg + (size_t)node * DH2;

    #pragma unroll 1
    for (int ch = 0; ch < 2; ch++) {
        float4 m[D_OUT / 4];
        #pragma unroll
        for (int j = 0; j < D_OUT / 4; j++) m[j] = *(const float4*)&bs[ch][j*4];

        const float* a   = arow + ch * DH;
        const float* wch = ws + ch * DH * D_OUT;
        #pragma unroll 4
        for (int k = 0; k < DH; k++) {
            float ak = a[k];
            const float* wrow = wch + k * D_OUT;
            #pragma unroll
            for (int j = 0; j < D_OUT / 4; j++) {
                float4 w = *(const float4*)&wrow[j*4];
                m[j].x = fmaf(ak, w.x, m[j].x);
                m[j].y = fmaf(ak, w.y, m[j].y);
                m[j].z = fmaf(ak, w.z, m[j].z);
                m[j].w = fmaf(ak, w.w, m[j].w);
            }
        }
        float ssq = 0.f;
        #pragma unroll
        for (int j = 0; j < D_OUT / 4; j++)
            ssq += m[j].x*m[j].x + m[j].y*m[j].y + m[j].z*m[j].z + m[j].w*m[j].w;
        float inv = 1.0f / fmaxf(sqrtf(ssq), 1e-12f);

        float4* o = (float4*)(out + (size_t)ch * N_NODES * D_OUT + (size_t)node * D_OUT);
        #pragma unroll
        for (int j = 0; j < D_OUT / 4; j++) {
            float4 r = m[j];
            r.x *= inv; r.y *= inv; r.z *= inv; r.w *= inv;
            o[j] = r;
        }
    }
}

// ---------------- launch ----------------
extern "C" void kernel_launch(void* const* d_in, const int* in_sizes, int n_in,
                              void* d_out, int out_size) {
    const float* x   = (const float*)d_in[0];
    const int*   ei  = (const int*)d_in[1];     // int32 (JAX x64 disabled)
    const float* W1  = (const float*)d_in[2];
    const float* b1  = (const float*)d_in[3];
    const float* W2  = (const float*)d_in[4];
    const float* b2  = (const float*)d_in[5];
    const float* Wl1 = (const float*)d_in[6];
    const float* bl1 = (const float*)d_in[7];
    const float* Wl2 = (const float*)d_in[8];
    const float* bl2 = (const float*)d_in[9];
    float* out = (float*)d_out;

    int E = in_sizes[1] / 2;
    if (E > EMAX) E = EMAX;
    const int* srcp = ei;
    const int* dstp = ei + E;

    k_zero  <<<(N_NODES + 255) / 256, 256>>>();
    k_count <<<(E + 255) / 256, 256>>>(dstp, E);
    k_scan  <<<1, SCT>>>();
    k_fill  <<<(E + 255) / 256, 256>>>(srcp, dstp, E);
    k_gemm  <<<(N_NODES + GR - 1) / GR, GT>>>(x, W1, W2);
    k_gather<<<(N_NODES + GA_NODES - 1) / GA_NODES, 320>>>(b1, b2);
    k_final <<<(N_NODES + 127) / 128, 128>>>(Wl1, bl1, Wl2, bl2, out);
}

// round 10
// speedup vs baseline: 1.0008x; 1.0001x over previous
#include <cuda_runtime.h>

#define N_NODES 100000
#define D_IN 512
#define DH 20
#define DH2 40
#define D_OUT 128
#define EMAX 3200000

// ---------------- scratch (device globals: no allocs allowed) ----------------
__device__ __align__(16) float g_xts[(size_t)N_NODES * DH2];  // (x@[W1|W2]) * dinv[row]
__device__ __align__(16) float g_agg[(size_t)N_NODES * DH2];  // aggregated + self + bias
__device__ float g_dinv[N_NODES];
__device__ int   g_deg [N_NODES];
__device__ int   g_cur [N_NODES];        // cursor, initialized to offsets by scan
__device__ int   g_off [N_NODES + 1];    // stable CSR offsets
__device__ int   g_sr  [EMAX];           // src per edge, CSR-ordered by dst

// ---------------- degree histogram ----------------
__global__ void k_zero() {
    int i = blockIdx.x * blockDim.x + threadIdx.x;
    if (i < N_NODES) g_deg[i] = 0;
}
__global__ void k_count(const int* __restrict__ dst, int E) {
    int e = blockIdx.x * blockDim.x + threadIdx.x;
    if (e < E) atomicAdd(&g_deg[dst[e]], 1);
}

// ---------------- exclusive scan (1 block) + dinv + cursor init -------------
#define SCT 1024
#define SCCH ((N_NODES + SCT - 1) / SCT)   // 98
__global__ __launch_bounds__(SCT) void k_scan() {
    __shared__ int sh[SCT];
    const int t = threadIdx.x;
    const int base = t * SCCH;
    int s = 0;
    for (int i = 0; i < SCCH; i++) {
        int idx = base + i;
        if (idx < N_NODES) s += g_deg[idx];
    }
    sh[t] = s;
    __syncthreads();
    for (int o = 1; o < SCT; o <<= 1) {
        int v = (t >= o) ? sh[t - o] : 0;
        __syncthreads();
        sh[t] += v;
        __syncthreads();
    }
    int run = sh[t] - s;   // exclusive prefix of this chunk
    for (int i = 0; i < SCCH; i++) {
        int idx = base + i;
        if (idx < N_NODES) {
            int d = g_deg[idx];
            g_off[idx]  = run;
            g_cur[idx]  = run;                       // cursor starts at offset
            g_dinv[idx] = rsqrtf((float)d + 1.0f);
            run += d;
        }
    }
    if (t == SCT - 1) g_off[N_NODES] = sh[SCT - 1];
}

// ---------------- CSR fill: src-only records, single atomic per edge --------
__global__ void k_fill(const int* __restrict__ src,
                       const int* __restrict__ dst, int E) {
    int e = blockIdx.x * blockDim.x + threadIdx.x;
    if (e >= E) return;
    int s = src[e];
    int d = dst[e];
    int pos = atomicAdd(&g_cur[d], 1);   // cursor pre-seeded with offset
    g_sr[pos] = s;
}

// ---------------- xts = (x @ [W1|W2]) * dinv  (fp32 FMA, float4 weights) ----
#define GT  64
#define GR  128
#define GKB 16

__global__ __launch_bounds__(GT) void k_gemm(
        const float* __restrict__ x,
        const float* __restrict__ W1,
        const float* __restrict__ W2) {
    __shared__ __align__(16) float  xs[GKB][GR + 4];   // transposed x tile
    __shared__ __align__(16) float4 ws4[GKB][DH2 / 4]; // weight chunk, vectorized

    const int tid  = threadIdx.x;
    const int row0 = blockIdx.x * GR;

    float acc0[DH2], acc1[DH2];
    #pragma unroll
    for (int c = 0; c < DH2; c++) { acc0[c] = 0.f; acc1[c] = 0.f; }

    for (int kb = 0; kb < D_IN; kb += GKB) {
        __syncthreads();
        // weight chunk: GKB*40 floats into float4-layout smem
        for (int i = tid; i < GKB * DH2; i += GT) {
            int kk = i / DH2, c = i % DH2;
            ((float*)ws4)[(size_t)kk * DH2 + c] =
                (c < DH) ? W1[(size_t)(kb + kk) * DH + c]
                         : W2[(size_t)(kb + kk) * DH + (c - DH)];
        }
        // x tile: 128 rows x 16 k, transposed into smem
        #pragma unroll
        for (int j = 0; j < GR / GT; j++) {
            int r  = tid + GT * j;
            int gr = row0 + r;
            if (gr < N_NODES) {
                const float4* srcp = (const float4*)(x + (size_t)gr * D_IN + kb);
                #pragma unroll
                for (int q = 0; q < GKB / 4; q++) {
                    float4 v = srcp[q];
                    xs[q*4+0][r] = v.x; xs[q*4+1][r] = v.y;
                    xs[q*4+2][r] = v.z; xs[q*4+3][r] = v.w;
                }
            } else {
                #pragma unroll
                for (int q = 0; q < GKB; q++) xs[q][r] = 0.f;
            }
        }
        __syncthreads();

        #pragma unroll 4
        for (int kk = 0; kk < GKB; kk++) {
            float2 xv = *(const float2*)&xs[kk][tid * 2];  // 2 rows, LDS.64
            #pragma unroll
            for (int j = 0; j < DH2 / 4; j++) {
                float4 w = ws4[kk][j];                      // LDS.128 broadcast
                acc0[j*4+0] = fmaf(xv.x, w.x, acc0[j*4+0]);
                acc0[j*4+1] = fmaf(xv.x, w.y, acc0[j*4+1]);
                acc0[j*4+2] = fmaf(xv.x, w.z, acc0[j*4+2]);
                acc0[j*4+3] = fmaf(xv.x, w.w, acc0[j*4+3]);
                acc1[j*4+0] = fmaf(xv.y, w.x, acc1[j*4+0]);
                acc1[j*4+1] = fmaf(xv.y, w.y, acc1[j*4+1]);
                acc1[j*4+2] = fmaf(xv.y, w.z, acc1[j*4+2]);
                acc1[j*4+3] = fmaf(xv.y, w.w, acc1[j*4+3]);
            }
        }
    }

    // epilogue: write xts = acc * dinv[row]
    #pragma unroll
    for (int h = 0; h < 2; h++) {
        int row = row0 + tid * 2 + h;
        if (row < N_NODES) {
            float di = g_dinv[row];
            float* xo = g_xts + (size_t)row * DH2;
            const float* ac = h ? acc1 : acc0;
            #pragma unroll
            for (int c4 = 0; c4 < DH2 / 4; c4++) {
                float4 vv;
                vv.x = ac[c4*4+0] * di; vv.y = ac[c4*4+1] * di;
                vv.z = ac[c4*4+2] * di; vv.w = ac[c4*4+3] * di;
                *(float4*)(xo + c4*4) = vv;
            }
        }
    }
}

// ---------------- gather: agg[n] = dinv[n]*(sum_e xts[src_e] + xts[n]) + b --
// 320 threads = 32 nodes x 10 quads; each (node,quad) owned by one thread.
#define GA_NODES 32
__global__ __launch_bounds__(320) void k_gather(const float* __restrict__ b1,
                                                const float* __restrict__ b2) {
    __shared__ float bsm[DH2];
    const int tid = threadIdx.x;
    if (tid < DH2) bsm[tid] = (tid < DH) ? b1[tid] : b2[tid - DH];
    __syncthreads();

    const int nl = tid / 10, q = tid % 10;
    const int n = blockIdx.x * GA_NODES + nl;
    if (n >= N_NODES) return;

    const int e0 = g_off[n], e1 = g_off[n + 1];
    const float4* selfq = (const float4*)(g_xts + (size_t)n * DH2 + q * 4);
    float4 acc = *selfq;    // self-loop term (xts[n]; scaled by dinv[n] below)

    int e = e0;
    for (; e + 1 < e1; e += 2) {
        int s0 = g_sr[e], s1 = g_sr[e + 1];
        float4 v0 = *(const float4*)(g_xts + (size_t)s0 * DH2 + q * 4);
        float4 v1 = *(const float4*)(g_xts + (size_t)s1 * DH2 + q * 4);
        acc.x += v0.x + v1.x; acc.y += v0.y + v1.y;
        acc.z += v0.z + v1.z; acc.w += v0.w + v1.w;
    }
    if (e < e1) {
        float4 v = *(const float4*)(g_xts + (size_t)g_sr[e] * DH2 + q * 4);
        acc.x += v.x; acc.y += v.y; acc.z += v.z; acc.w += v.w;
    }

    float di = g_dinv[n];
    float4 bq = *(const float4*)&bsm[q * 4];
    float4 r;
    r.x = fmaf(acc.x, di, bq.x); r.y = fmaf(acc.y, di, bq.y);
    r.z = fmaf(acc.z, di, bq.z); r.w = fmaf(acc.w, di, bq.w);
    *(float4*)(g_agg + (size_t)n * DH2 + q * 4) = r;
}

// ---------------- m = agg @ Wl + bl ; l2norm ----------------
__global__ __launch_bounds__(128) void k_final(
        const float* __restrict__ Wl1, const float* __restrict__ bl1,
        const float* __restrict__ Wl2, const float* __restrict__ bl2,
        float* __restrict__ out) {
    __shared__ __align__(16) float ws[2 * DH * D_OUT];
    __shared__ __align__(16) float bs[2][D_OUT];
    const int tid = threadIdx.x;

    for (int i = tid; i < DH * D_OUT; i += 128) {
        ws[i]              = Wl1[i];
        ws[DH * D_OUT + i] = Wl2[i];
    }
    bs[0][tid] = bl1[tid];
    bs[1][tid] = bl2[tid];
    __syncthreads();

    int node = blockIdx.x * 128 + tid;
    if (node >= N_NODES) return;
    const float* arow = g_agg + (size_t)node * DH2;

    #pragma unroll 1
    for (int ch = 0; ch < 2; ch++) {
        float4 m[D_OUT / 4];
        #pragma unroll
        for (int j = 0; j < D_OUT / 4; j++) m[j] = *(const float4*)&bs[ch][j*4];

        const float* a   = arow + ch * DH;
        const float* wch = ws + ch * DH * D_OUT;
        #pragma unroll 4
        for (int k = 0; k < DH; k++) {
            float ak = a[k];
            const float* wrow = wch + k * D_OUT;
            #pragma unroll
            for (int j = 0; j < D_OUT / 4; j++) {
                float4 w = *(const float4*)&wrow[j*4];
                m[j].x = fmaf(ak, w.x, m[j].x);
                m[j].y = fmaf(ak, w.y, m[j].y);
                m[j].z = fmaf(ak, w.z, m[j].z);
                m[j].w = fmaf(ak, w.w, m[j].w);
            }
        }
        float ssq = 0.f;
        #pragma unroll
        for (int j = 0; j < D_OUT / 4; j++)
            ssq += m[j].x*m[j].x + m[j].y*m[j].y + m[j].z*m[j].z + m[j].w*m[j].w;
        float inv = 1.0f / fmaxf(sqrtf(ssq), 1e-12f);

        float4* o = (float4*)(out + (size_t)ch * N_NODES * D_OUT + (size_t)node * D_OUT);
        #pragma unroll
        for (int j = 0; j < D_OUT / 4; j++) {
            float4 r = m[j];
            r.x *= inv; r.y *= inv; r.z *= inv; r.w *= inv;
            o[j] = r;
        }
    }
}

// ---------------- launch ----------------
extern "C" void kernel_launch(void* const* d_in, const int* in_sizes, int n_in,
                              void* d_out, int out_size) {
    const float* x   = (const float*)d_in[0];
    const int*   ei  = (const int*)d_in[1];     // int32 (JAX x64 disabled)
    const float* W1  = (const float*)d_in[2];
    const float* b1  = (const float*)d_in[3];
    const float* W2  = (const float*)d_in[4];
    const float* b2  = (const float*)d_in[5];
    const float* Wl1 = (const float*)d_in[6];
    const float* bl1 = (const float*)d_in[7];
    const float* Wl2 = (const float*)d_in[8];
    const float* bl2 = (const float*)d_in[9];
    float* out = (float*)d_out;

    int E = in_sizes[1] / 2;
    if (E > EMAX) E = EMAX;
    const int* srcp = ei;
    const int* dstp = ei + E;

    k_zero  <<<(N_NODES + 255) / 256, 256>>>();
    k_count <<<(E + 255) / 256, 256>>>(dstp, E);
    k_scan  <<<1, SCT>>>();
    k_fill  <<<(E + 255) / 256, 256>>>(srcp, dstp, E);
    k_gemm  <<<(N_NODES + GR - 1) / GR, GT>>>(x, W1, W2);
    k_gather<<<(N_NODES + GA_NODES - 1) / GA_NODES, 320>>>(b1, b2);
    k_final <<<(N_NODES + 127) / 128, 128>>>(Wl1, bl1, Wl2, bl2, out);
}

// round 11
// speedup vs baseline: 1.0011x; 1.0004x over previous
#include <cuda_runtime.h>

#define N_NODES 100000
#define D_IN 512
#define DH 20
#define DH2 40
#define D_OUT 128
#define EMAX 3200000

// ---------------- scratch (device globals: no allocs allowed) ----------------
__device__ __align__(16) float g_xts[(size_t)N_NODES * DH2];  // (x@[W1|W2]) * dinv[row]
__device__ __align__(16) float g_agg[(size_t)N_NODES * DH2];  // aggregated + self + bias
__device__ float g_dinv[N_NODES];
__device__ int   g_deg [N_NODES];
__device__ int   g_cur [N_NODES];        // cursor, initialized to offsets by scan
__device__ int   g_off [N_NODES + 1];    // stable CSR offsets
__device__ int   g_sr  [EMAX];           // src per edge, CSR-ordered by dst

// ---------------- degree histogram ----------------
__global__ void k_zero() {
    int i = blockIdx.x * blockDim.x + threadIdx.x;
    if (i < N_NODES) g_deg[i] = 0;
}
__global__ void k_count(const int* __restrict__ dst, int E) {
    int e = blockIdx.x * blockDim.x + threadIdx.x;
    if (e < E) atomicAdd(&g_deg[dst[e]], 1);
}

// ---------------- exclusive scan (1 block) + dinv + cursor init -------------
#define SCT 1024
#define SCCH ((N_NODES + SCT - 1) / SCT)   // 98
__global__ __launch_bounds__(SCT) void k_scan() {
    __shared__ int sh[SCT];
    const int t = threadIdx.x;
    const int base = t * SCCH;
    int s = 0;
    for (int i = 0; i < SCCH; i++) {
        int idx = base + i;
        if (idx < N_NODES) s += g_deg[idx];
    }
    sh[t] = s;
    __syncthreads();
    for (int o = 1; o < SCT; o <<= 1) {
        int v = (t >= o) ? sh[t - o] : 0;
        __syncthreads();
        sh[t] += v;
        __syncthreads();
    }
    int run = sh[t] - s;   // exclusive prefix of this chunk
    for (int i = 0; i < SCCH; i++) {
        int idx = base + i;
        if (idx < N_NODES) {
            int d = g_deg[idx];
            g_off[idx]  = run;
            g_cur[idx]  = run;                       // cursor starts at offset
            g_dinv[idx] = rsqrtf((float)d + 1.0f);
            run += d;
        }
    }
    if (t == SCT - 1) g_off[N_NODES] = sh[SCT - 1];
}

// ---------------- CSR fill: src-only records, single atomic per edge --------
__global__ void k_fill(const int* __restrict__ src,
                       const int* __restrict__ dst, int E) {
    int e = blockIdx.x * blockDim.x + threadIdx.x;
    if (e >= E) return;
    int s = src[e];
    int d = dst[e];
    int pos = atomicAdd(&g_cur[d], 1);   // cursor pre-seeded with offset
    g_sr[pos] = s;
}

// ---------------- xts = (x @ [W1|W2]) * dinv  (fp32 FMA, float4 weights) ----
#define GT  64
#define GR  128
#define GKB 16

__global__ __launch_bounds__(GT) void k_gemm(
        const float* __restrict__ x,
        const float* __restrict__ W1,
        const float* __restrict__ W2) {
    __shared__ __align__(16) float  xs[GKB][GR + 4];   // transposed x tile
    __shared__ __align__(16) float4 ws4[GKB][DH2 / 4]; // weight chunk, vectorized

    const int tid  = threadIdx.x;
    const int row0 = blockIdx.x * GR;

    float acc0[DH2], acc1[DH2];
    #pragma unroll
    for (int c = 0; c < DH2; c++) { acc0[c] = 0.f; acc1[c] = 0.f; }

    for (int kb = 0; kb < D_IN; kb += GKB) {
        __syncthreads();
        // weight chunk: GKB*40 floats into float4-layout smem
        for (int i = tid; i < GKB * DH2; i += GT) {
            int kk = i / DH2, c = i % DH2;
            ((float*)ws4)[(size_t)kk * DH2 + c] =
                (c < DH) ? W1[(size_t)(kb + kk) * DH + c]
                         : W2[(size_t)(kb + kk) * DH + (c - DH)];
        }
        // x tile: 128 rows x 16 k, transposed into smem
        #pragma unroll
        for (int j = 0; j < GR / GT; j++) {
            int r  = tid + GT * j;
            int gr = row0 + r;
            if (gr < N_NODES) {
                const float4* srcp = (const float4*)(x + (size_t)gr * D_IN + kb);
                #pragma unroll
                for (int q = 0; q < GKB / 4; q++) {
                    float4 v = srcp[q];
                    xs[q*4+0][r] = v.x; xs[q*4+1][r] = v.y;
                    xs[q*4+2][r] = v.z; xs[q*4+3][r] = v.w;
                }
            } else {
                #pragma unroll
                for (int q = 0; q < GKB; q++) xs[q][r] = 0.f;
            }
        }
        __syncthreads();

        #pragma unroll 4
        for (int kk = 0; kk < GKB; kk++) {
            float2 xv = *(const float2*)&xs[kk][tid * 2];  // 2 rows, LDS.64
            #pragma unroll
            for (int j = 0; j < DH2 / 4; j++) {
                float4 w = ws4[kk][j];                      // LDS.128 broadcast
                acc0[j*4+0] = fmaf(xv.x, w.x, acc0[j*4+0]);
                acc0[j*4+1] = fmaf(xv.x, w.y, acc0[j*4+1]);
                acc0[j*4+2] = fmaf(xv.x, w.z, acc0[j*4+2]);
                acc0[j*4+3] = fmaf(xv.x, w.w, acc0[j*4+3]);
                acc1[j*4+0] = fmaf(xv.y, w.x, acc1[j*4+0]);
                acc1[j*4+1] = fmaf(xv.y, w.y, acc1[j*4+1]);
                acc1[j*4+2] = fmaf(xv.y, w.z, acc1[j*4+2]);
                acc1[j*4+3] = fmaf(xv.y, w.w, acc1[j*4+3]);
            }
        }
    }

    // epilogue: write xts = acc * dinv[row]
    #pragma unroll
    for (int h = 0; h < 2; h++) {
        int row = row0 + tid * 2 + h;
        if (row < N_NODES) {
            float di = g_dinv[row];
            float* xo = g_xts + (size_t)row * DH2;
            const float* ac = h ? acc1 : acc0;
            #pragma unroll
            for (int c4 = 0; c4 < DH2 / 4; c4++) {
                float4 vv;
                vv.x = ac[c4*4+0] * di; vv.y = ac[c4*4+1] * di;
                vv.z = ac[c4*4+2] * di; vv.w = ac[c4*4+3] * di;
                *(float4*)(xo + c4*4) = vv;
            }
        }
    }
}

// ---------------- gather: agg[n] = dinv[n]*(sum_e xts[src_e] + xts[n]) + b --
// 320 threads = 32 nodes x 10 quads; each (node,quad) owned by one thread.
#define GA_NODES 32
__global__ __launch_bounds__(320) void k_gather(const float* __restrict__ b1,
                                                const float* __restrict__ b2) {
    __shared__ float bsm[DH2];
    const int tid = threadIdx.x;
    if (tid < DH2) bsm[tid] = (tid < DH) ? b1[tid] : b2[tid - DH];
    __syncthreads();

    const int nl = tid / 10, q = tid % 10;
    const int n = blockIdx.x * GA_NODES + nl;
    if (n >= N_NODES) return;

    const int e0 = g_off[n], e1 = g_off[n + 1];
    const float4* selfq = (const float4*)(g_xts + (size_t)n * DH2 + q * 4);
    float4 acc = *selfq;    // self-loop term (xts[n]; scaled by dinv[n] below)

    int e = e0;
    for (; e + 1 < e1; e += 2) {
        int s0 = g_sr[e], s1 = g_sr[e + 1];
        float4 v0 = *(const float4*)(g_xts + (size_t)s0 * DH2 + q * 4);
        float4 v1 = *(const float4*)(g_xts + (size_t)s1 * DH2 + q * 4);
        acc.x += v0.x + v1.x; acc.y += v0.y + v1.y;
        acc.z += v0.z + v1.z; acc.w += v0.w + v1.w;
    }
    if (e < e1) {
        float4 v = *(const float4*)(g_xts + (size_t)g_sr[e] * DH2 + q * 4);
        acc.x += v.x; acc.y += v.y; acc.z += v.z; acc.w += v.w;
    }

    float di = g_dinv[n];
    float4 bq = *(const float4*)&bsm[q * 4];
    float4 r;
    r.x = fmaf(acc.x, di, bq.x); r.y = fmaf(acc.y, di, bq.y);
    r.z = fmaf(acc.z, di, bq.z); r.w = fmaf(acc.w, di, bq.w);
    *(float4*)(g_agg + (size_t)n * DH2 + q * 4) = r;
}

// ---------------- m = agg @ Wl + bl ; l2norm ----------------
__global__ __launch_bounds__(128) void k_final(
        const float* __restrict__ Wl1, const float* __restrict__ bl1,
        const float* __restrict__ Wl2, const float* __restrict__ bl2,
        float* __restrict__ out) {
    __shared__ __align__(16) float ws[2 * DH * D_OUT];
    __shared__ __align__(16) float bs[2][D_OUT];
    const int tid = threadIdx.x;

    for (int i = tid; i < DH * D_OUT; i += 128) {
        ws[i]              = Wl1[i];
        ws[DH * D_OUT + i] = Wl2[i];
    }
    bs[0][tid] = bl1[tid];
    bs[1][tid] = bl2[tid];
    __syncthreads();

    int node = blockIdx.x * 128 + tid;
    if (node >= N_NODES) return;
    const float* arow = g_agg + (size_t)node * DH2;

    #pragma unroll 1
    for (int ch = 0; ch < 2; ch++) {
        float4 m[D_OUT / 4];
        #pragma unroll
        for (int j = 0; j < D_OUT / 4; j++) m[j] = *(const float4*)&bs[ch][j*4];

        const float* a   = arow + ch * DH;
        const float* wch = ws + ch * DH * D_OUT;
        #pragma unroll 4
        for (int k = 0; k < DH; k++) {
            float ak = a[k];
            const float* wrow = wch + k * D_OUT;
            #pragma unroll
            for (int j = 0; j < D_OUT / 4; j++) {
                float4 w = *(const float4*)&wrow[j*4];
                m[j].x = fmaf(ak, w.x, m[j].x);
                m[j].y = fmaf(ak, w.y, m[j].y);
                m[j].z = fmaf(ak, w.z, m[j].z);
                m[j].w = fmaf(ak, w.w, m[j].w);
            }
        }
        float ssq = 0.f;
        #pragma unroll
        for (int j = 0; j < D_OUT / 4; j++)
            ssq += m[j].x*m[j].x + m[j].y*m[j].y + m[j].z*m[j].z + m[j].w*m[j].w;
        float inv = 1.0f / fmaxf(sqrtf(ssq), 1e-12f);

        float4* o = (float4*)(out + (size_t)ch * N_NODES * D_OUT + (size_t)node * D_OUT);
        #pragma unroll
        for (int j = 0; j < D_OUT / 4; j++) {
            float4 r = m[j];
            r.x *= inv; r.y *= inv; r.z *= inv; r.w *= inv;
            o[j] = r;
        }
    }
}

// ---------------- launch ----------------
extern "C" void kernel_launch(void* const* d_in, const int* in_sizes, int n_in,
                              void* d_out, int out_size) {
    const float* x   = (const float*)d_in[0];
    const int*   ei  = (const int*)d_in[1];     // int32 (JAX x64 disabled)
    const float* W1  = (const float*)d_in[2];
    const float* b1  = (const float*)d_in[3];
    const float* W2  = (const float*)d_in[4];
    const float* b2  = (const float*)d_in[5];
    const float* Wl1 = (const float*)d_in[6];
    const float* bl1 = (const float*)d_in[7];
    const float* Wl2 = (const float*)d_in[8];
    const float* bl2 = (const float*)d_in[9];
    float* out = (float*)d_out;

    int E = in_sizes[1] / 2;
    if (E > EMAX) E = EMAX;
    const int* srcp = ei;
    const int* dstp = ei + E;

    k_zero  <<<(N_NODES + 255) / 256, 256>>>();
    k_count <<<(E + 255) / 256, 256>>>(dstp, E);
    k_scan  <<<1, SCT>>>();
    k_fill  <<<(E + 255) / 256, 256>>>(srcp, dstp, E);
    k_gemm  <<<(N_NODES + GR - 1) / GR, GT>>>(x, W1, W2);
    k_gather<<<(N_NODES + GA_NODES - 1) / GA_NODES, 320>>>(b1, b2);
    k_final <<<(N_NODES + 127) / 128, 128>>>(Wl1, bl1, Wl2, bl2, out);
}

// round 12
// speedup vs baseline: 1.4245x; 1.4229x over previous
#include <cuda_runtime.h>

#define N_NODES 100000
#define D_IN 512
#define DH 20
#define DH2 40
#define D_OUT 128
#define EMAX 3200000

// ---------------- scratch (device globals: no allocs allowed) ----------------
__device__ __align__(16) float g_xt [(size_t)N_NODES * DH2];  // x@[W1|W2] (unscaled)
__device__ __align__(16) float g_xts[(size_t)N_NODES * DH2];  // g_xt * dinv[row]
__device__ __align__(16) float g_agg[(size_t)N_NODES * DH2];  // aggregated + self + bias
__device__ float g_dinv[N_NODES];
__device__ int   g_deg [N_NODES];
__device__ int   g_cur [N_NODES];        // cursor, initialized to offsets by scan
__device__ int   g_off [N_NODES + 1];    // stable CSR offsets
__device__ int   g_sr  [EMAX];           // src per edge, CSR-ordered by dst

// ---------------- degree histogram ----------------
__global__ void k_zero() {
    int i = blockIdx.x * blockDim.x + threadIdx.x;
    if (i < N_NODES) g_deg[i] = 0;
}
__global__ void k_count(const int* __restrict__ dst, int E) {
    int e = blockIdx.x * blockDim.x + threadIdx.x;
    if (e < E) atomicAdd(&g_deg[dst[e]], 1);
}

// ---------------- exclusive scan (1 block) + dinv + cursor init -------------
#define SCT 1024
#define SCCH ((N_NODES + SCT - 1) / SCT)   // 98
__global__ __launch_bounds__(SCT) void k_scan() {
    __shared__ int sh[SCT];
    const int t = threadIdx.x;
    const int base = t * SCCH;
    int s = 0;
    for (int i = 0; i < SCCH; i++) {
        int idx = base + i;
        if (idx < N_NODES) s += g_deg[idx];
    }
    sh[t] = s;
    __syncthreads();
    for (int o = 1; o < SCT; o <<= 1) {
        int v = (t >= o) ? sh[t - o] : 0;
        __syncthreads();
        sh[t] += v;
        __syncthreads();
    }
    int run = sh[t] - s;   // exclusive prefix of this chunk
    for (int i = 0; i < SCCH; i++) {
        int idx = base + i;
        if (idx < N_NODES) {
            int d = g_deg[idx];
            g_off[idx]  = run;
            g_cur[idx]  = run;                       // cursor starts at offset
            g_dinv[idx] = rsqrtf((float)d + 1.0f);
            run += d;
        }
    }
    if (t == SCT - 1) g_off[N_NODES] = sh[SCT - 1];
}

// ---------------- CSR fill: src-only records, single atomic per edge --------
__global__ void k_fill(const int* __restrict__ src,
                       const int* __restrict__ dst, int E) {
    int e = blockIdx.x * blockDim.x + threadIdx.x;
    if (e >= E) return;
    int s = src[e];
    int d = dst[e];
    int pos = atomicAdd(&g_cur[d], 1);   // cursor pre-seeded with offset
    g_sr[pos] = s;
}

// ---------------- xt = x @ [W1|W2]  (no dinv dep -> overlaps CSR chain) ----
#define GT  64
#define GR  128
#define GKB 16

__global__ __launch_bounds__(GT) void k_gemm(
        const float* __restrict__ x,
        const float* __restrict__ W1,
        const float* __restrict__ W2) {
    __shared__ __align__(16) float  xs[GKB][GR + 4];   // transposed x tile
    __shared__ __align__(16) float4 ws4[GKB][DH2 / 4]; // weight chunk, vectorized

    const int tid  = threadIdx.x;
    const int row0 = blockIdx.x * GR;

    float acc0[DH2], acc1[DH2];
    #pragma unroll
    for (int c = 0; c < DH2; c++) { acc0[c] = 0.f; acc1[c] = 0.f; }

    for (int kb = 0; kb < D_IN; kb += GKB) {
        __syncthreads();
        for (int i = tid; i < GKB * DH2; i += GT) {
            int kk = i / DH2, c = i % DH2;
            ((float*)ws4)[(size_t)kk * DH2 + c] =
                (c < DH) ? W1[(size_t)(kb + kk) * DH + c]
                         : W2[(size_t)(kb + kk) * DH + (c - DH)];
        }
        #pragma unroll
        for (int j = 0; j < GR / GT; j++) {
            int r  = tid + GT * j;
            int gr = row0 + r;
            if (gr < N_NODES) {
                const float4* srcp = (const float4*)(x + (size_t)gr * D_IN + kb);
                #pragma unroll
                for (int q = 0; q < GKB / 4; q++) {
                    float4 v = srcp[q];
                    xs[q*4+0][r] = v.x; xs[q*4+1][r] = v.y;
                    xs[q*4+2][r] = v.z; xs[q*4+3][r] = v.w;
                }
            } else {
                #pragma unroll
                for (int q = 0; q < GKB; q++) xs[q][r] = 0.f;
            }
        }
        __syncthreads();

        #pragma unroll 4
        for (int kk = 0; kk < GKB; kk++) {
            float2 xv = *(const float2*)&xs[kk][tid * 2];  // 2 rows, LDS.64
            #pragma unroll
            for (int j = 0; j < DH2 / 4; j++) {
                float4 w = ws4[kk][j];                      // LDS.128 broadcast
                acc0[j*4+0] = fmaf(xv.x, w.x, acc0[j*4+0]);
                acc0[j*4+1] = fmaf(xv.x, w.y, acc0[j*4+1]);
                acc0[j*4+2] = fmaf(xv.x, w.z, acc0[j*4+2]);
                acc0[j*4+3] = fmaf(xv.x, w.w, acc0[j*4+3]);
                acc1[j*4+0] = fmaf(xv.y, w.x, acc1[j*4+0]);
                acc1[j*4+1] = fmaf(xv.y, w.y, acc1[j*4+1]);
                acc1[j*4+2] = fmaf(xv.y, w.z, acc1[j*4+2]);
                acc1[j*4+3] = fmaf(xv.y, w.w, acc1[j*4+3]);
            }
        }
    }

    #pragma unroll
    for (int h = 0; h < 2; h++) {
        int row = row0 + tid * 2 + h;
        if (row < N_NODES) {
            float* xo = g_xt + (size_t)row * DH2;
            const float* ac = h ? acc1 : acc0;
            #pragma unroll
            for (int c4 = 0; c4 < DH2 / 4; c4++) {
                float4 vv;
                vv.x = ac[c4*4+0]; vv.y = ac[c4*4+1];
                vv.z = ac[c4*4+2]; vv.w = ac[c4*4+3];
                *(float4*)(xo + c4*4) = vv;
            }
        }
    }
}

// ---------------- xts = xt * dinv[row]  (tiny elementwise, after join) ------
__global__ __launch_bounds__(256) void k_scale() {
    int i = blockIdx.x * blockDim.x + threadIdx.x;   // one float4 per thread
    if (i >= N_NODES * (DH2 / 4)) return;
    int row = i / (DH2 / 4);
    float di = g_dinv[row];
    float4 v = *((const float4*)g_xt + i);
    v.x *= di; v.y *= di; v.z *= di; v.w *= di;
    *((float4*)g_xts + i) = v;
}

// ---------------- gather: agg[n] = dinv[n]*(sum_e xts[src_e] + xts[n]) + b --
// 320 threads = 32 nodes x 10 quads; each (node,quad) owned by one thread.
#define GA_NODES 32
__global__ __launch_bounds__(320) void k_gather(const float* __restrict__ b1,
                                                const float* __restrict__ b2) {
    __shared__ float bsm[DH2];
    const int tid = threadIdx.x;
    if (tid < DH2) bsm[tid] = (tid < DH) ? b1[tid] : b2[tid - DH];
    __syncthreads();

    const int nl = tid / 10, q = tid % 10;
    const int n = blockIdx.x * GA_NODES + nl;
    if (n >= N_NODES) return;

    const int e0 = g_off[n], e1 = g_off[n + 1];
    float4 acc = *(const float4*)(g_xts + (size_t)n * DH2 + q * 4);  // self-loop

    int e = e0;
    for (; e + 4 <= e1; e += 4) {            // MLP-4: indices first, then rows
        int s0 = g_sr[e], s1 = g_sr[e+1], s2 = g_sr[e+2], s3 = g_sr[e+3];
        float4 v0 = *(const float4*)(g_xts + (size_t)s0 * DH2 + q * 4);
        float4 v1 = *(const float4*)(g_xts + (size_t)s1 * DH2 + q * 4);
        float4 v2 = *(const float4*)(g_xts + (size_t)s2 * DH2 + q * 4);
        float4 v3 = *(const float4*)(g_xts + (size_t)s3 * DH2 + q * 4);
        acc.x += (v0.x + v1.x) + (v2.x + v3.x);
        acc.y += (v0.y + v1.y) + (v2.y + v3.y);
        acc.z += (v0.z + v1.z) + (v2.z + v3.z);
        acc.w += (v0.w + v1.w) + (v2.w + v3.w);
    }
    for (; e < e1; e++) {
        float4 v = *(const float4*)(g_xts + (size_t)g_sr[e] * DH2 + q * 4);
        acc.x += v.x; acc.y += v.y; acc.z += v.z; acc.w += v.w;
    }

    float di = g_dinv[n];
    float4 bq = *(const float4*)&bsm[q * 4];
    float4 r;
    r.x = fmaf(acc.x, di, bq.x); r.y = fmaf(acc.y, di, bq.y);
    r.z = fmaf(acc.z, di, bq.z); r.w = fmaf(acc.w, di, bq.w);
    *(float4*)(g_agg + (size_t)n * DH2 + q * 4) = r;
}

// ---------------- m = agg @ Wl + bl ; l2norm ----------------
__global__ __launch_bounds__(128) void k_final(
        const float* __restrict__ Wl1, const float* __restrict__ bl1,
        const float* __restrict__ Wl2, const float* __restrict__ bl2,
        float* __restrict__ out) {
    __shared__ __align__(16) float ws[2 * DH * D_OUT];
    __shared__ __align__(16) float bs[2][D_OUT];
    const int tid = threadIdx.x;

    for (int i = tid; i < DH * D_OUT; i += 128) {
        ws[i]              = Wl1[i];
        ws[DH * D_OUT + i] = Wl2[i];
    }
    bs[0][tid] = bl1[tid];
    bs[1][tid] = bl2[tid];
    __syncthreads();

    int node = blockIdx.x * 128 + tid;
    if (node >= N_NODES) return;
    const float* arow = g_agg + (size_t)node * DH2;

    #pragma unroll 1
    for (int ch = 0; ch < 2; ch++) {
        float4 m[D_OUT / 4];
        #pragma unroll
        for (int j = 0; j < D_OUT / 4; j++) m[j] = *(const float4*)&bs[ch][j*4];

        const float* a   = arow + ch * DH;
        const float* wch = ws + ch * DH * D_OUT;
        #pragma unroll 4
        for (int k = 0; k < DH; k++) {
            float ak = a[k];
            const float* wrow = wch + k * D_OUT;
            #pragma unroll
            for (int j = 0; j < D_OUT / 4; j++) {
                float4 w = *(const float4*)&wrow[j*4];
                m[j].x = fmaf(ak, w.x, m[j].x);
                m[j].y = fmaf(ak, w.y, m[j].y);
                m[j].z = fmaf(ak, w.z, m[j].z);
                m[j].w = fmaf(ak, w.w, m[j].w);
            }
        }
        float ssq = 0.f;
        #pragma unroll
        for (int j = 0; j < D_OUT / 4; j++)
            ssq += m[j].x*m[j].x + m[j].y*m[j].y + m[j].z*m[j].z + m[j].w*m[j].w;
        float inv = 1.0f / fmaxf(sqrtf(ssq), 1e-12f);

        float4* o = (float4*)(out + (size_t)ch * N_NODES * D_OUT + (size_t)node * D_OUT);
        #pragma unroll
        for (int j = 0; j < D_OUT / 4; j++) {
            float4 r = m[j];
            r.x *= inv; r.y *= inv; r.z *= inv; r.w *= inv;
            o[j] = r;
        }
    }
}

// ---------------- launch: fork CSR chain onto side stream -------------------
extern "C" void kernel_launch(void* const* d_in, const int* in_sizes, int n_in,
                              void* d_out, int out_size) {
    const float* x   = (const float*)d_in[0];
    const int*   ei  = (const int*)d_in[1];     // int32 (JAX x64 disabled)
    const float* W1  = (const float*)d_in[2];
    const float* b1  = (const float*)d_in[3];
    const float* W2  = (const float*)d_in[4];
    const float* b2  = (const float*)d_in[5];
    const float* Wl1 = (const float*)d_in[6];
    const float* bl1 = (const float*)d_in[7];
    const float* Wl2 = (const float*)d_in[8];
    const float* bl2 = (const float*)d_in[9];
    float* out = (float*)d_out;

    int E = in_sizes[1] / 2;
    if (E > EMAX) E = EMAX;
    const int* srcp = ei;
    const int* dstp = ei + E;

    // one-time resource creation (no device memory involved)
    static cudaStream_t s_side = nullptr;
    static cudaEvent_t  ev_fork = nullptr, ev_join = nullptr;
    if (s_side == nullptr) {
        cudaStreamCreateWithFlags(&s_side, cudaStreamNonBlocking);
        cudaEventCreateWithFlags(&ev_fork, cudaEventDisableTiming);
        cudaEventCreateWithFlags(&ev_join, cudaEventDisableTiming);
    }

    // fork: CSR chain on side stream, GEMM on main stream (independent)
    cudaEventRecord(ev_fork, 0);
    cudaStreamWaitEvent(s_side, ev_fork, 0);

    k_zero  <<<(N_NODES + 255) / 256, 256, 0, s_side>>>();
    k_count <<<(E + 255) / 256, 256, 0, s_side>>>(dstp, E);
    k_scan  <<<1, SCT, 0, s_side>>>();
    k_fill  <<<(E + 255) / 256, 256, 0, s_side>>>(srcp, dstp, E);
    cudaEventRecord(ev_join, s_side);

    k_gemm  <<<(N_NODES + GR - 1) / GR, GT>>>(x, W1, W2);

    // join: everything below needs both branches
    cudaStreamWaitEvent(0, ev_join, 0);

    k_scale <<<(N_NODES * (DH2 / 4) + 255) / 256, 256>>>();
    k_gather<<<(N_NODES + GA_NODES - 1) / GA_NODES, 320>>>(b1, b2);
    k_final <<<(N_NODES + 127) / 128, 128>>>(Wl1, bl1, Wl2, bl2, out);
}